// round 15
// baseline (speedup 1.0000x reference)
#include <cuda_runtime.h>
#include <cuda_fp16.h>

// SSIM loss, fused separable 11x11 Gaussian, B=64, H=W=512.
// R15: single-kernel (ticket-fused finalize; zero/finalize launches deleted)
//      + THREADS=128 with 8 CTAs/SM (same 32 warps, finer-grained barrier
//      absorption). Math identical to R14: direct-GMEM stage B, f16 4-plane
//      v units, padded conflict-free layout, scatter FFMA-imm stage C.

#define BATCH 64
#define IMG_H 512
#define IMG_W 512
#define TH 32
#define HALO 5
#define NCP 38                // col-pairs per padded row
#define THREADS 128
#define TILES_X 8
#define TILES_Y 16
#define NBLOCKS (BATCH * TILES_X * TILES_Y)   // 8192

#define VROW_B 768            // padded row stride: 48 units * 16B (6 x 128B)
#define SMEM_BYTES (TH * VROW_B)   // 24576 -> 8 CTAs/SM

#define NSLOTS 32
#define SLOT_STRIDE 16

typedef unsigned long long u64;

// Gaussian(ks=11, sigma=1.5), normalized.
#define W0 0.00102838f
#define W1 0.00759876f
#define W2 0.03600077f
#define W3 0.10936069f
#define W4 0.21300553f
#define W5 0.26601172f
__device__ __constant__ float c_w[11] = {W0,W1,W2,W3,W4,W5,W4,W3,W2,W1,W0};

// Compile-time weight lookup (folds to FFMA immediates).
#define CWK(k) ((k)==0?W0:(k)==1?W1:(k)==2?W2:(k)==3?W3:(k)==4?W4: \
                (k)==5?W5:(k)==6?W4:(k)==7?W3:(k)==8?W2:(k)==9?W1:W0)

__device__ double g_slots[NSLOTS * SLOT_STRIDE];   // static zero-init
__device__ unsigned g_ticket;                      // static zero-init

__device__ __forceinline__ unsigned smem_u32(const void* p) {
    unsigned r;
    asm("{ .reg .u64 t; cvta.to.shared.u64 t, %1; cvt.u32.u64 %0, t; }"
        : "=r"(r) : "l"(p));
    return r;
}
__device__ __forceinline__ u64 pack2(float lo, float hi) {
    u64 r; asm("mov.b64 %0, {%1,%2};" : "=l"(r) : "f"(lo), "f"(hi)); return r;
}
__device__ __forceinline__ void unpack2(u64 v, float& a, float& b) {
    asm("mov.b64 {%0,%1}, %2;" : "=f"(a), "=f"(b) : "l"(v));
}
__device__ __forceinline__ u64 fma2(u64 a, u64 b, u64 c) {
    u64 d; asm("fma.rn.f32x2 %0, %1, %2, %3;" : "=l"(d) : "l"(a), "l"(b), "l"(c));
    return d;
}
__device__ __forceinline__ u64 mul2(u64 a, u64 b) {
    u64 d; asm("mul.rn.f32x2 %0, %1, %2;" : "=l"(d) : "l"(a), "l"(b)); return d;
}
__device__ __forceinline__ u64 ldg64(const float* p) {
    u64 r; asm volatile("ld.global.nc.b64 %0, [%1];" : "=l"(r) : "l"(p));
    return r;
}
__device__ __forceinline__ uint4 lds128u(unsigned addr) {
    uint4 q;
    asm volatile("ld.shared.v4.b32 {%0,%1,%2,%3}, [%4];"
                 : "=r"(q.x), "=r"(q.y), "=r"(q.z), "=r"(q.w) : "r"(addr));
    return q;
}
__device__ __forceinline__ void sts128u(unsigned addr, unsigned a, unsigned b,
                                        unsigned c, unsigned d) {
    asm volatile("st.shared.v4.b32 [%0], {%1,%2,%3,%4};"
                 :: "r"(addr), "r"(a), "r"(b), "r"(c), "r"(d));
}
__device__ __forceinline__ unsigned f2h2(u64 v) {
    float lo, hi;
    unpack2(v, lo, hi);
    __half2 h = __floats2half2_rn(lo, hi);
    return *reinterpret_cast<unsigned*>(&h);
}
__device__ __forceinline__ float2 h22f2(unsigned u) {
    __half2 h = *reinterpret_cast<__half2*>(&u);
    return __half22float2(h);
}

__global__ __launch_bounds__(THREADS, 8)
void ssim_main_k(const float* __restrict__ x, const float* __restrict__ y,
                 float* __restrict__ out) {
    extern __shared__ float smem[];
    const unsigned vb = smem_u32(smem);

    const int tid = threadIdx.x;
    const int blk = blockIdx.x;
    const int b  = blk >> 7;
    const int t  = blk & 127;
    const int ty = t >> 3;
    const int tx = t & 7;
    const int gx0 = tx * 64 - 6;          // EVEN left edge (covers halo -5)
    const int gy0 = ty * TH - HALO;

    const float* __restrict__ xb = x + (size_t)b * IMG_H * IMG_W;
    const float* __restrict__ yb = y + (size_t)b * IMG_H * IMG_W;

    // ---- Stage B: vertical conv {x, y, x2+y2, xy} straight from GMEM.
    //      304 items = 8 strips x 38 col-pairs, 4-row strips, 14 rows each.
    {
        u64 w2[6];   // symmetric: w[k] == w[10-k]
        #pragma unroll
        for (int k = 0; k < 6; k++) w2[k] = pack2(c_w[k], c_w[k]);

        const bool interior = (gx0 >= 0) & (gx0 + 2 * NCP <= IMG_W) &
                              (gy0 >= 0) & (gy0 + TH + 10 <= IMG_H);

        for (int e = tid; e < 8 * NCP; e += THREADS) {
            int rs = e / NCP;
            int cp = e - rs * NCP;
            int r0 = rs * 4;

            u64 s0[4] = {0,0,0,0};
            u64 s1[4] = {0,0,0,0};
            u64 s2[4] = {0,0,0,0};
            u64 s3[4] = {0,0,0,0};

            if (interior) {
                const float* xp = xb + (size_t)(gy0 + r0) * IMG_W + (gx0 + 2 * cp);
                const float* yp = yb + (size_t)(gy0 + r0) * IMG_W + (gx0 + 2 * cp);
                #pragma unroll
                for (int j = 0; j < 14; j++) {
                    u64 a  = ldg64(xp + j * IMG_W);
                    u64 bb = ldg64(yp + j * IMG_W);
                    u64 ab = mul2(a, bb);
                    u64 qq = fma2(a, a, mul2(bb, bb));
                    #pragma unroll
                    for (int tt = 0; tt < 4; tt++) {
                        int k = j - tt;
                        if (k >= 0 && k <= 10) {
                            u64 wk = w2[(k <= 5) ? k : 10 - k];
                            s0[tt] = fma2(wk, a,  s0[tt]);
                            s1[tt] = fma2(wk, bb, s1[tt]);
                            s2[tt] = fma2(wk, qq, s2[tt]);
                            s3[tt] = fma2(wk, ab, s3[tt]);
                        }
                    }
                }
            } else {
                int c0 = gx0 + 2 * cp;
                #pragma unroll
                for (int j = 0; j < 14; j++) {
                    int gy = gy0 + r0 + j;
                    float x0 = 0.f, x1 = 0.f, y0 = 0.f, y1 = 0.f;
                    if ((unsigned)gy < IMG_H) {
                        size_t rowb = (size_t)gy * IMG_W;
                        if ((unsigned)c0 < IMG_W) { x0 = xb[rowb + c0]; y0 = yb[rowb + c0]; }
                        if ((unsigned)(c0 + 1) < IMG_W) { x1 = xb[rowb + c0 + 1]; y1 = yb[rowb + c0 + 1]; }
                    }
                    u64 a  = pack2(x0, x1);
                    u64 bb = pack2(y0, y1);
                    u64 ab = mul2(a, bb);
                    u64 qq = fma2(a, a, mul2(bb, bb));
                    #pragma unroll
                    for (int tt = 0; tt < 4; tt++) {
                        int k = j - tt;
                        if (k >= 0 && k <= 10) {
                            u64 wk = w2[(k <= 5) ? k : 10 - k];
                            s0[tt] = fma2(wk, a,  s0[tt]);
                            s1[tt] = fma2(wk, bb, s1[tt]);
                            s2[tt] = fma2(wk, qq, s2[tt]);
                            s3[tt] = fma2(wk, ab, s3[tt]);
                        }
                    }
                }
            }
            // padded unit position: p = cp + cp/4 (1 pad per 4 units)
            const unsigned pcol = (unsigned)((cp + (cp >> 2)) << 4);
            #pragma unroll
            for (int tt = 0; tt < 4; tt++) {
                unsigned sa = vb + (unsigned)((r0 + tt) * VROW_B) + pcol;
                sts128u(sa, f2h2(s0[tt]), f2h2(s1[tt]), f2h2(s2[tt]), f2h2(s3[tt]));
            }
        }
    }
    __syncthreads();

    // ---- Stage C: 256 units = 32 rows x 8 qblocks; 2 units per thread.
    //      Single pass over 10-entry window; scatter FFMA-imm.
    float lsum = 0.f;
    #pragma unroll
    for (int uu = 0; uu < 2; uu++) {
        const int unit = tid + uu * THREADS;
        const int r  = unit >> 3;        // 0..31
        const int qb = unit & 7;         // output cols 8qb .. 8qb+7
        const unsigned base = vb + (unsigned)(r * VROW_B) + (unsigned)(qb * 80);

        float mx[8], my[8], m2[8], m3[8];
        #pragma unroll
        for (int c = 0; c < 8; c++) { mx[c]=0.f; my[c]=0.f; m2[c]=0.f; m3[c]=0.f; }

        #pragma unroll
        for (int i = 0; i < 10; i++) {
            uint4 q = lds128u(base + (unsigned)((i + (i >> 2)) << 4));
            float2 fx = h22f2(q.x);
            float2 fy = h22f2(q.y);
            float2 f2 = h22f2(q.z);
            float2 f3 = h22f2(q.w);
            #pragma unroll
            for (int h = 0; h < 2; h++) {
                const int jj = 2 * i + h;
                const float va  = h ? fx.y : fx.x;
                const float vb2 = h ? fy.y : fy.x;
                const float vc  = h ? f2.y : f2.x;
                const float vd  = h ? f3.y : f3.x;
                #pragma unroll
                for (int c = 0; c < 8; c++) {
                    const int k = jj - 1 - c;
                    if (k >= 0 && k <= 10) {
                        mx[c] = fmaf(CWK(k), va,  mx[c]);
                        my[c] = fmaf(CWK(k), vb2, my[c]);
                        m2[c] = fmaf(CWK(k), vc,  m2[c]);
                        m3[c] = fmaf(CWK(k), vd,  m3[c]);
                    }
                }
            }
        }

        const float C1 = 1e-4f, C2 = 9e-4f;
        #pragma unroll
        for (int c = 0; c < 8; c++) {
            float muxy = mx[c] * my[c];
            float S    = fmaf(mx[c], mx[c], my[c] * my[c]);
            float B1 = S + C1;
            float B2 = (m2[c] - S) + C2;
            float A1 = fmaf(2.f, muxy, C1);
            float A2 = fmaf(2.f, m3[c] - muxy, C2);
            lsum += __fdividef(A1 * A2, fmaf(B1, B2, 1e-12f));
        }
    }

    // ---- Block reduction (4 warps) + slot atomic ----
    #pragma unroll
    for (int off = 16; off > 0; off >>= 1)
        lsum += __shfl_down_sync(0xFFFFFFFFu, lsum, off);

    __syncthreads();
    float* red = smem;
    int warp = tid >> 5, lane = tid & 31;
    if (lane == 0) red[warp] = lsum;
    __syncthreads();
    __shared__ unsigned s_last;
    if (tid == 0) {
        float v = red[0] + red[1] + red[2] + red[3];
        atomicAdd(&g_slots[(blk & (NSLOTS - 1)) * SLOT_STRIDE], (double)v);
        __threadfence();
        unsigned tk = atomicAdd(&g_ticket, 1u);
        s_last = (tk == NBLOCKS - 1) ? 1u : 0u;
    }
    __syncthreads();

    // ---- Fused finalize: last CTA sums slots, writes out, resets state ----
    if (s_last && tid < 32) {
        __threadfence();
        double v = g_slots[tid * SLOT_STRIDE];
        g_slots[tid * SLOT_STRIDE] = 0.0;      // reset for next graph replay
        #pragma unroll
        for (int off = 16; off > 0; off >>= 1)
            v += __shfl_down_sync(0xFFFFFFFFu, v, off);
        if (tid == 0) {
            out[0] = (float)(1.0 - v / ((double)BATCH * IMG_H * IMG_W));
            g_ticket = 0u;                     // reset ticket
        }
    }
}

extern "C" void kernel_launch(void* const* d_in, const int* in_sizes, int n_in,
                              void* d_out, int out_size) {
    (void)in_sizes; (void)n_in; (void)out_size;
    const float* x = (const float*)d_in[0];
    const float* y = (const float*)d_in[1];
    float* out = (float*)d_out;

    static bool attr_set = false;
    if (!attr_set) {
        cudaFuncSetAttribute(ssim_main_k,
                             cudaFuncAttributeMaxDynamicSharedMemorySize,
                             SMEM_BYTES);
        attr_set = true;
    }

    ssim_main_k<<<NBLOCKS, THREADS, SMEM_BYTES>>>(x, y, out);
}

// round 16
// speedup vs baseline: 1.0975x; 1.0975x over previous
#include <cuda_runtime.h>
#include <cuda_fp16.h>

// SSIM loss, fused separable 11x11 Gaussian, B=64, H=W=512.
// R16: R14 compute config restored (THREADS=256, 4 CTAs/SM — R15's 128-thread
//      split regressed via stage-B imbalance + L2 thrash) + R15's fused
//      ticket finalize kept (single launch). Direct-GMEM stage B, f16
//      4-plane v units, padded conflict-free layout, scatter FFMA-imm stage C.

#define BATCH 64
#define IMG_H 512
#define IMG_W 512
#define TH 32
#define HALO 5
#define NCP 38                // col-pairs per padded row
#define THREADS 256
#define TILES_X 8
#define TILES_Y 16
#define NBLOCKS (BATCH * TILES_X * TILES_Y)   // 8192

#define VROW_B 768            // padded row stride: 48 units * 16B (6 x 128B)
#define SMEM_BYTES (TH * VROW_B)   // 24576 -> 4 CTAs/SM (reg-limited)

#define NSLOTS 32
#define SLOT_STRIDE 16

typedef unsigned long long u64;

// Gaussian(ks=11, sigma=1.5), normalized.
#define W0 0.00102838f
#define W1 0.00759876f
#define W2 0.03600077f
#define W3 0.10936069f
#define W4 0.21300553f
#define W5 0.26601172f
__device__ __constant__ float c_w[11] = {W0,W1,W2,W3,W4,W5,W4,W3,W2,W1,W0};

// Compile-time weight lookup (folds to FFMA immediates).
#define CWK(k) ((k)==0?W0:(k)==1?W1:(k)==2?W2:(k)==3?W3:(k)==4?W4: \
                (k)==5?W5:(k)==6?W4:(k)==7?W3:(k)==8?W2:(k)==9?W1:W0)

__device__ double g_slots[NSLOTS * SLOT_STRIDE];   // static zero-init
__device__ unsigned g_ticket;                      // static zero-init

__device__ __forceinline__ unsigned smem_u32(const void* p) {
    unsigned r;
    asm("{ .reg .u64 t; cvta.to.shared.u64 t, %1; cvt.u32.u64 %0, t; }"
        : "=r"(r) : "l"(p));
    return r;
}
__device__ __forceinline__ u64 pack2(float lo, float hi) {
    u64 r; asm("mov.b64 %0, {%1,%2};" : "=l"(r) : "f"(lo), "f"(hi)); return r;
}
__device__ __forceinline__ void unpack2(u64 v, float& a, float& b) {
    asm("mov.b64 {%0,%1}, %2;" : "=f"(a), "=f"(b) : "l"(v));
}
__device__ __forceinline__ u64 fma2(u64 a, u64 b, u64 c) {
    u64 d; asm("fma.rn.f32x2 %0, %1, %2, %3;" : "=l"(d) : "l"(a), "l"(b), "l"(c));
    return d;
}
__device__ __forceinline__ u64 mul2(u64 a, u64 b) {
    u64 d; asm("mul.rn.f32x2 %0, %1, %2;" : "=l"(d) : "l"(a), "l"(b)); return d;
}
__device__ __forceinline__ u64 ldg64(const float* p) {
    u64 r; asm volatile("ld.global.nc.b64 %0, [%1];" : "=l"(r) : "l"(p));
    return r;
}
__device__ __forceinline__ uint4 lds128u(unsigned addr) {
    uint4 q;
    asm volatile("ld.shared.v4.b32 {%0,%1,%2,%3}, [%4];"
                 : "=r"(q.x), "=r"(q.y), "=r"(q.z), "=r"(q.w) : "r"(addr));
    return q;
}
__device__ __forceinline__ void sts128u(unsigned addr, unsigned a, unsigned b,
                                        unsigned c, unsigned d) {
    asm volatile("st.shared.v4.b32 [%0], {%1,%2,%3,%4};"
                 :: "r"(addr), "r"(a), "r"(b), "r"(c), "r"(d));
}
__device__ __forceinline__ unsigned f2h2(u64 v) {
    float lo, hi;
    unpack2(v, lo, hi);
    __half2 h = __floats2half2_rn(lo, hi);
    return *reinterpret_cast<unsigned*>(&h);
}
__device__ __forceinline__ float2 h22f2(unsigned u) {
    __half2 h = *reinterpret_cast<__half2*>(&u);
    return __half22float2(h);
}

__global__ __launch_bounds__(THREADS, 4)
void ssim_main_k(const float* __restrict__ x, const float* __restrict__ y,
                 float* __restrict__ out) {
    extern __shared__ float smem[];
    const unsigned vb = smem_u32(smem);

    const int tid = threadIdx.x;
    const int blk = blockIdx.x;
    const int b  = blk >> 7;
    const int t  = blk & 127;
    const int ty = t >> 3;
    const int tx = t & 7;
    const int gx0 = tx * 64 - 6;          // EVEN left edge (covers halo -5)
    const int gy0 = ty * TH - HALO;

    const float* __restrict__ xb = x + (size_t)b * IMG_H * IMG_W;
    const float* __restrict__ yb = y + (size_t)b * IMG_H * IMG_W;

    // ---- Stage B: vertical conv {x, y, x2+y2, xy} straight from GMEM.
    //      304 items = 8 strips x 38 col-pairs, 4-row strips, 14 rows each.
    //      Output: one 16B f16 unit per (row, col-pair): (mux|muy|m2|m3).
    {
        u64 w2[6];   // symmetric: w[k] == w[10-k]
        #pragma unroll
        for (int k = 0; k < 6; k++) w2[k] = pack2(c_w[k], c_w[k]);

        const bool interior = (gx0 >= 0) & (gx0 + 2 * NCP <= IMG_W) &
                              (gy0 >= 0) & (gy0 + TH + 10 <= IMG_H);

        for (int e = tid; e < 8 * NCP; e += THREADS) {
            int rs = e / NCP;
            int cp = e - rs * NCP;
            int r0 = rs * 4;

            u64 s0[4] = {0,0,0,0};
            u64 s1[4] = {0,0,0,0};
            u64 s2[4] = {0,0,0,0};
            u64 s3[4] = {0,0,0,0};

            if (interior) {
                const float* xp = xb + (size_t)(gy0 + r0) * IMG_W + (gx0 + 2 * cp);
                const float* yp = yb + (size_t)(gy0 + r0) * IMG_W + (gx0 + 2 * cp);
                #pragma unroll
                for (int j = 0; j < 14; j++) {
                    u64 a  = ldg64(xp + j * IMG_W);
                    u64 bb = ldg64(yp + j * IMG_W);
                    u64 ab = mul2(a, bb);
                    u64 qq = fma2(a, a, mul2(bb, bb));
                    #pragma unroll
                    for (int tt = 0; tt < 4; tt++) {
                        int k = j - tt;
                        if (k >= 0 && k <= 10) {
                            u64 wk = w2[(k <= 5) ? k : 10 - k];
                            s0[tt] = fma2(wk, a,  s0[tt]);
                            s1[tt] = fma2(wk, bb, s1[tt]);
                            s2[tt] = fma2(wk, qq, s2[tt]);
                            s3[tt] = fma2(wk, ab, s3[tt]);
                        }
                    }
                }
            } else {
                int c0 = gx0 + 2 * cp;
                #pragma unroll
                for (int j = 0; j < 14; j++) {
                    int gy = gy0 + r0 + j;
                    float x0 = 0.f, x1 = 0.f, y0 = 0.f, y1 = 0.f;
                    if ((unsigned)gy < IMG_H) {
                        size_t rowb = (size_t)gy * IMG_W;
                        if ((unsigned)c0 < IMG_W) { x0 = xb[rowb + c0]; y0 = yb[rowb + c0]; }
                        if ((unsigned)(c0 + 1) < IMG_W) { x1 = xb[rowb + c0 + 1]; y1 = yb[rowb + c0 + 1]; }
                    }
                    u64 a  = pack2(x0, x1);
                    u64 bb = pack2(y0, y1);
                    u64 ab = mul2(a, bb);
                    u64 qq = fma2(a, a, mul2(bb, bb));
                    #pragma unroll
                    for (int tt = 0; tt < 4; tt++) {
                        int k = j - tt;
                        if (k >= 0 && k <= 10) {
                            u64 wk = w2[(k <= 5) ? k : 10 - k];
                            s0[tt] = fma2(wk, a,  s0[tt]);
                            s1[tt] = fma2(wk, bb, s1[tt]);
                            s2[tt] = fma2(wk, qq, s2[tt]);
                            s3[tt] = fma2(wk, ab, s3[tt]);
                        }
                    }
                }
            }
            // padded unit position: p = cp + cp/4 (1 pad per 4 units)
            const unsigned pcol = (unsigned)((cp + (cp >> 2)) << 4);
            #pragma unroll
            for (int tt = 0; tt < 4; tt++) {
                unsigned sa = vb + (unsigned)((r0 + tt) * VROW_B) + pcol;
                sts128u(sa, f2h2(s0[tt]), f2h2(s1[tt]), f2h2(s2[tt]), f2h2(s3[tt]));
            }
        }
    }
    __syncthreads();

    // ---- Stage C: 256 units = 32 rows x 8 qblocks, 1 unit/thread.
    //      Single pass over 10-entry window; scatter FFMA-imm.
    float lsum = 0.f;
    {
        const int r  = tid >> 3;         // 0..31
        const int qb = tid & 7;          // output cols 8qb .. 8qb+7
        const unsigned base = vb + (unsigned)(r * VROW_B) + (unsigned)(qb * 80);

        float mx[8], my[8], m2[8], m3[8];
        #pragma unroll
        for (int c = 0; c < 8; c++) { mx[c]=0.f; my[c]=0.f; m2[c]=0.f; m3[c]=0.f; }

        #pragma unroll
        for (int i = 0; i < 10; i++) {
            uint4 q = lds128u(base + (unsigned)((i + (i >> 2)) << 4));
            float2 fx = h22f2(q.x);
            float2 fy = h22f2(q.y);
            float2 f2 = h22f2(q.z);
            float2 f3 = h22f2(q.w);
            #pragma unroll
            for (int h = 0; h < 2; h++) {
                const int jj = 2 * i + h;
                const float va  = h ? fx.y : fx.x;
                const float vb2 = h ? fy.y : fy.x;
                const float vc  = h ? f2.y : f2.x;
                const float vd  = h ? f3.y : f3.x;
                #pragma unroll
                for (int c = 0; c < 8; c++) {
                    const int k = jj - 1 - c;
                    if (k >= 0 && k <= 10) {
                        mx[c] = fmaf(CWK(k), va,  mx[c]);
                        my[c] = fmaf(CWK(k), vb2, my[c]);
                        m2[c] = fmaf(CWK(k), vc,  m2[c]);
                        m3[c] = fmaf(CWK(k), vd,  m3[c]);
                    }
                }
            }
        }

        const float C1 = 1e-4f, C2 = 9e-4f;
        #pragma unroll
        for (int c = 0; c < 8; c++) {
            float muxy = mx[c] * my[c];
            float S    = fmaf(mx[c], mx[c], my[c] * my[c]);
            float B1 = S + C1;
            float B2 = (m2[c] - S) + C2;
            float A1 = fmaf(2.f, muxy, C1);
            float A2 = fmaf(2.f, m3[c] - muxy, C2);
            lsum += __fdividef(A1 * A2, fmaf(B1, B2, 1e-12f));
        }
    }

    // ---- Block reduction (8 warps) + slot atomic ----
    #pragma unroll
    for (int off = 16; off > 0; off >>= 1)
        lsum += __shfl_down_sync(0xFFFFFFFFu, lsum, off);

    __syncthreads();
    float* red = smem;
    int warp = tid >> 5, lane = tid & 31;
    if (lane == 0) red[warp] = lsum;
    __syncthreads();
    __shared__ unsigned s_last;
    if (tid == 0) {
        float v = red[0] + red[1] + red[2] + red[3]
                + red[4] + red[5] + red[6] + red[7];
        atomicAdd(&g_slots[(blk & (NSLOTS - 1)) * SLOT_STRIDE], (double)v);
        __threadfence();
        unsigned tk = atomicAdd(&g_ticket, 1u);
        s_last = (tk == NBLOCKS - 1) ? 1u : 0u;
    }
    __syncthreads();

    // ---- Fused finalize: last CTA sums slots, writes out, resets state ----
    if (s_last && tid < 32) {
        __threadfence();
        double v = g_slots[tid * SLOT_STRIDE];
        g_slots[tid * SLOT_STRIDE] = 0.0;      // reset for next graph replay
        #pragma unroll
        for (int off = 16; off > 0; off >>= 1)
            v += __shfl_down_sync(0xFFFFFFFFu, v, off);
        if (tid == 0) {
            out[0] = (float)(1.0 - v / ((double)BATCH * IMG_H * IMG_W));
            g_ticket = 0u;                     // reset ticket
        }
    }
}

extern "C" void kernel_launch(void* const* d_in, const int* in_sizes, int n_in,
                              void* d_out, int out_size) {
    (void)in_sizes; (void)n_in; (void)out_size;
    const float* x = (const float*)d_in[0];
    const float* y = (const float*)d_in[1];
    float* out = (float*)d_out;

    static bool attr_set = false;
    if (!attr_set) {
        cudaFuncSetAttribute(ssim_main_k,
                             cudaFuncAttributeMaxDynamicSharedMemorySize,
                             SMEM_BYTES);
        attr_set = true;
    }

    ssim_main_k<<<NBLOCKS, THREADS, SMEM_BYTES>>>(x, y, out);
}

// round 17
// speedup vs baseline: 1.1632x; 1.0599x over previous
#include <cuda_runtime.h>
#include <cuda_fp16.h>

// SSIM loss, fused separable 11x11 Gaussian, B=64, H=W=512.
// R17: R14 main kernel restored exactly (no ticket/fence — R16 showed the
//      grid-wide ticket + threadfence costs ~8us in-kernel, more than the
//      launches it saves). Epilogue collapsed to ONE kernel: finalize reads
//      slots, writes out, and RESETS slots for the next graph replay
//      (static zero-init covers the first call). 2 launches total.

#define BATCH 64
#define IMG_H 512
#define IMG_W 512
#define TH 32
#define HALO 5
#define NCP 38                // col-pairs per padded row
#define THREADS 256
#define TILES_X 8
#define TILES_Y 16
#define NBLOCKS (BATCH * TILES_X * TILES_Y)   // 8192

#define VROW_B 768            // padded row stride: 48 units * 16B (6 x 128B)
#define SMEM_BYTES (TH * VROW_B)   // 24576 -> 4 CTAs/SM (reg-limited)

#define NSLOTS 32
#define SLOT_STRIDE 16

typedef unsigned long long u64;

// Gaussian(ks=11, sigma=1.5), normalized.
#define W0 0.00102838f
#define W1 0.00759876f
#define W2 0.03600077f
#define W3 0.10936069f
#define W4 0.21300553f
#define W5 0.26601172f
__device__ __constant__ float c_w[11] = {W0,W1,W2,W3,W4,W5,W4,W3,W2,W1,W0};

// Compile-time weight lookup (folds to FFMA immediates).
#define CWK(k) ((k)==0?W0:(k)==1?W1:(k)==2?W2:(k)==3?W3:(k)==4?W4: \
                (k)==5?W5:(k)==6?W4:(k)==7?W3:(k)==8?W2:(k)==9?W1:W0)

__device__ double g_slots[NSLOTS * SLOT_STRIDE];   // static zero-init

__device__ __forceinline__ unsigned smem_u32(const void* p) {
    unsigned r;
    asm("{ .reg .u64 t; cvta.to.shared.u64 t, %1; cvt.u32.u64 %0, t; }"
        : "=r"(r) : "l"(p));
    return r;
}
__device__ __forceinline__ u64 pack2(float lo, float hi) {
    u64 r; asm("mov.b64 %0, {%1,%2};" : "=l"(r) : "f"(lo), "f"(hi)); return r;
}
__device__ __forceinline__ void unpack2(u64 v, float& a, float& b) {
    asm("mov.b64 {%0,%1}, %2;" : "=f"(a), "=f"(b) : "l"(v));
}
__device__ __forceinline__ u64 fma2(u64 a, u64 b, u64 c) {
    u64 d; asm("fma.rn.f32x2 %0, %1, %2, %3;" : "=l"(d) : "l"(a), "l"(b), "l"(c));
    return d;
}
__device__ __forceinline__ u64 mul2(u64 a, u64 b) {
    u64 d; asm("mul.rn.f32x2 %0, %1, %2;" : "=l"(d) : "l"(a), "l"(b)); return d;
}
__device__ __forceinline__ u64 ldg64(const float* p) {
    u64 r; asm volatile("ld.global.nc.b64 %0, [%1];" : "=l"(r) : "l"(p));
    return r;
}
__device__ __forceinline__ uint4 lds128u(unsigned addr) {
    uint4 q;
    asm volatile("ld.shared.v4.b32 {%0,%1,%2,%3}, [%4];"
                 : "=r"(q.x), "=r"(q.y), "=r"(q.z), "=r"(q.w) : "r"(addr));
    return q;
}
__device__ __forceinline__ void sts128u(unsigned addr, unsigned a, unsigned b,
                                        unsigned c, unsigned d) {
    asm volatile("st.shared.v4.b32 [%0], {%1,%2,%3,%4};"
                 :: "r"(addr), "r"(a), "r"(b), "r"(c), "r"(d));
}
__device__ __forceinline__ unsigned f2h2(u64 v) {
    float lo, hi;
    unpack2(v, lo, hi);
    __half2 h = __floats2half2_rn(lo, hi);
    return *reinterpret_cast<unsigned*>(&h);
}
__device__ __forceinline__ float2 h22f2(unsigned u) {
    __half2 h = *reinterpret_cast<__half2*>(&u);
    return __half22float2(h);
}

// Single epilogue: read slots, write result, reset slots for next replay.
__global__ void ssim_finalize_k(float* out) {
    int t = threadIdx.x;
    double v = g_slots[t * SLOT_STRIDE];
    g_slots[t * SLOT_STRIDE] = 0.0;
    #pragma unroll
    for (int off = 16; off > 0; off >>= 1)
        v += __shfl_down_sync(0xFFFFFFFFu, v, off);
    if (t == 0)
        out[0] = (float)(1.0 - v / ((double)BATCH * IMG_H * IMG_W));
}

__global__ __launch_bounds__(THREADS, 4)
void ssim_main_k(const float* __restrict__ x, const float* __restrict__ y) {
    extern __shared__ float smem[];
    const unsigned vb = smem_u32(smem);

    const int tid = threadIdx.x;
    const int blk = blockIdx.x;
    const int b  = blk >> 7;
    const int t  = blk & 127;
    const int ty = t >> 3;
    const int tx = t & 7;
    const int gx0 = tx * 64 - 6;          // EVEN left edge (covers halo -5)
    const int gy0 = ty * TH - HALO;

    const float* __restrict__ xb = x + (size_t)b * IMG_H * IMG_W;
    const float* __restrict__ yb = y + (size_t)b * IMG_H * IMG_W;

    // ---- Stage B: vertical conv {x, y, x2+y2, xy} straight from GMEM.
    //      304 items = 8 strips x 38 col-pairs, 4-row strips, 14 rows each.
    {
        u64 w2[6];   // symmetric: w[k] == w[10-k]
        #pragma unroll
        for (int k = 0; k < 6; k++) w2[k] = pack2(c_w[k], c_w[k]);

        const bool interior = (gx0 >= 0) & (gx0 + 2 * NCP <= IMG_W) &
                              (gy0 >= 0) & (gy0 + TH + 10 <= IMG_H);

        for (int e = tid; e < 8 * NCP; e += THREADS) {
            int rs = e / NCP;
            int cp = e - rs * NCP;
            int r0 = rs * 4;

            u64 s0[4] = {0,0,0,0};
            u64 s1[4] = {0,0,0,0};
            u64 s2[4] = {0,0,0,0};
            u64 s3[4] = {0,0,0,0};

            if (interior) {
                const float* xp = xb + (size_t)(gy0 + r0) * IMG_W + (gx0 + 2 * cp);
                const float* yp = yb + (size_t)(gy0 + r0) * IMG_W + (gx0 + 2 * cp);
                #pragma unroll
                for (int j = 0; j < 14; j++) {
                    u64 a  = ldg64(xp + j * IMG_W);
                    u64 bb = ldg64(yp + j * IMG_W);
                    u64 ab = mul2(a, bb);
                    u64 qq = fma2(a, a, mul2(bb, bb));
                    #pragma unroll
                    for (int tt = 0; tt < 4; tt++) {
                        int k = j - tt;
                        if (k >= 0 && k <= 10) {
                            u64 wk = w2[(k <= 5) ? k : 10 - k];
                            s0[tt] = fma2(wk, a,  s0[tt]);
                            s1[tt] = fma2(wk, bb, s1[tt]);
                            s2[tt] = fma2(wk, qq, s2[tt]);
                            s3[tt] = fma2(wk, ab, s3[tt]);
                        }
                    }
                }
            } else {
                int c0 = gx0 + 2 * cp;
                #pragma unroll
                for (int j = 0; j < 14; j++) {
                    int gy = gy0 + r0 + j;
                    float x0 = 0.f, x1 = 0.f, y0 = 0.f, y1 = 0.f;
                    if ((unsigned)gy < IMG_H) {
                        size_t rowb = (size_t)gy * IMG_W;
                        if ((unsigned)c0 < IMG_W) { x0 = xb[rowb + c0]; y0 = yb[rowb + c0]; }
                        if ((unsigned)(c0 + 1) < IMG_W) { x1 = xb[rowb + c0 + 1]; y1 = yb[rowb + c0 + 1]; }
                    }
                    u64 a  = pack2(x0, x1);
                    u64 bb = pack2(y0, y1);
                    u64 ab = mul2(a, bb);
                    u64 qq = fma2(a, a, mul2(bb, bb));
                    #pragma unroll
                    for (int tt = 0; tt < 4; tt++) {
                        int k = j - tt;
                        if (k >= 0 && k <= 10) {
                            u64 wk = w2[(k <= 5) ? k : 10 - k];
                            s0[tt] = fma2(wk, a,  s0[tt]);
                            s1[tt] = fma2(wk, bb, s1[tt]);
                            s2[tt] = fma2(wk, qq, s2[tt]);
                            s3[tt] = fma2(wk, ab, s3[tt]);
                        }
                    }
                }
            }
            // padded unit position: p = cp + cp/4 (1 pad per 4 units)
            const unsigned pcol = (unsigned)((cp + (cp >> 2)) << 4);
            #pragma unroll
            for (int tt = 0; tt < 4; tt++) {
                unsigned sa = vb + (unsigned)((r0 + tt) * VROW_B) + pcol;
                sts128u(sa, f2h2(s0[tt]), f2h2(s1[tt]), f2h2(s2[tt]), f2h2(s3[tt]));
            }
        }
    }
    __syncthreads();

    // ---- Stage C: 256 units = 32 rows x 8 qblocks, 1 unit/thread.
    //      Single pass over 10-entry window; scatter FFMA-imm.
    float lsum = 0.f;
    {
        const int r  = tid >> 3;         // 0..31
        const int qb = tid & 7;          // output cols 8qb .. 8qb+7
        const unsigned base = vb + (unsigned)(r * VROW_B) + (unsigned)(qb * 80);

        float mx[8], my[8], m2[8], m3[8];
        #pragma unroll
        for (int c = 0; c < 8; c++) { mx[c]=0.f; my[c]=0.f; m2[c]=0.f; m3[c]=0.f; }

        #pragma unroll
        for (int i = 0; i < 10; i++) {
            uint4 q = lds128u(base + (unsigned)((i + (i >> 2)) << 4));
            float2 fx = h22f2(q.x);
            float2 fy = h22f2(q.y);
            float2 f2 = h22f2(q.z);
            float2 f3 = h22f2(q.w);
            #pragma unroll
            for (int h = 0; h < 2; h++) {
                const int jj = 2 * i + h;
                const float va  = h ? fx.y : fx.x;
                const float vb2 = h ? fy.y : fy.x;
                const float vc  = h ? f2.y : f2.x;
                const float vd  = h ? f3.y : f3.x;
                #pragma unroll
                for (int c = 0; c < 8; c++) {
                    const int k = jj - 1 - c;
                    if (k >= 0 && k <= 10) {
                        mx[c] = fmaf(CWK(k), va,  mx[c]);
                        my[c] = fmaf(CWK(k), vb2, my[c]);
                        m2[c] = fmaf(CWK(k), vc,  m2[c]);
                        m3[c] = fmaf(CWK(k), vd,  m3[c]);
                    }
                }
            }
        }

        const float C1 = 1e-4f, C2 = 9e-4f;
        #pragma unroll
        for (int c = 0; c < 8; c++) {
            float muxy = mx[c] * my[c];
            float S    = fmaf(mx[c], mx[c], my[c] * my[c]);
            float B1 = S + C1;
            float B2 = (m2[c] - S) + C2;
            float A1 = fmaf(2.f, muxy, C1);
            float A2 = fmaf(2.f, m3[c] - muxy, C2);
            lsum += __fdividef(A1 * A2, fmaf(B1, B2, 1e-12f));
        }
    }

    // ---- Block reduction (8 warps) + slot atomic ----
    #pragma unroll
    for (int off = 16; off > 0; off >>= 1)
        lsum += __shfl_down_sync(0xFFFFFFFFu, lsum, off);

    __syncthreads();
    float* red = smem;
    int warp = tid >> 5, lane = tid & 31;
    if (lane == 0) red[warp] = lsum;
    __syncthreads();
    if (warp == 0) {
        float v = (lane < (THREADS / 32)) ? red[lane] : 0.f;
        #pragma unroll
        for (int off = 4; off > 0; off >>= 1)
            v += __shfl_down_sync(0xFFFFFFFFu, v, off);
        if (lane == 0)
            atomicAdd(&g_slots[(blk & (NSLOTS - 1)) * SLOT_STRIDE], (double)v);
    }
}

extern "C" void kernel_launch(void* const* d_in, const int* in_sizes, int n_in,
                              void* d_out, int out_size) {
    (void)in_sizes; (void)n_in; (void)out_size;
    const float* x = (const float*)d_in[0];
    const float* y = (const float*)d_in[1];
    float* out = (float*)d_out;

    static bool attr_set = false;
    if (!attr_set) {
        cudaFuncSetAttribute(ssim_main_k,
                             cudaFuncAttributeMaxDynamicSharedMemorySize,
                             SMEM_BYTES);
        attr_set = true;
    }

    // Slots are zero on entry (static init on first call; finalize resets
    // them on every call). Two launches total.
    ssim_main_k<<<NBLOCKS, THREADS, SMEM_BYTES>>>(x, y);
    ssim_finalize_k<<<1, 32>>>(out);
}